// round 8
// baseline (speedup 1.0000x reference)
#include <cuda_runtime.h>

// Problem constants
#define Bn  64
#define An  5
#define Cn  80
#define Hn  52
#define Wn  52
#define Tn  32
#define HWn (Hn * Wn)          // 2704
#define QWn (HWn / 4)          // 676 float4s per plane
#define NUNITS (Bn * An * QWn) // 216320 vec4 units

#define TGT_BLOCKS 256          // 2048 warps / 8
#define NEG_BLOCKS 423          // ceil(216320 / 512)
#define GRID (TGT_BLOCKS + NEG_BLOCKS)

// Persistent scratch (zero at module load; final block resets after each run)
__device__ float        g_scratch[5];
__device__ unsigned int g_count;

__device__ __forceinline__ float softplusf_(float x) {
    // max(x,0) + log(1 + exp(-|x|));  EX2 + LG2, abs err ~1e-7
    return fmaxf(x, 0.f) + __logf(1.f + __expf(-fabsf(x)));
}
__device__ __forceinline__ float fsigmoid(float x) {
    // sigmoid(x) = 0.5 + 0.5*tanh(x/2) — HW MUFU.TANH, abs err ~1e-5
    float t;
    asm("tanh.approx.f32 %0, %1;" : "=f"(t) : "f"(x * 0.5f));
    return fmaf(t, 0.5f, 0.5f);
}

__device__ __forceinline__ void ticket_and_finalize(float* __restrict__ out) {
    __shared__ bool is_last;
    __threadfence();
    if (threadIdx.x == 0) {
        unsigned prev = atomicAdd(&g_count, 1u);
        is_last = (prev == GRID - 1);
    }
    __syncthreads();
    if (is_last) {
        __threadfence();
        if (threadIdx.x < 5) {
            volatile float* vs = g_scratch;
            out[threadIdx.x] = vs[threadIdx.x];
            g_scratch[threadIdx.x] = 0.f;
        }
        if (threadIdx.x == 0) g_count = 0u;
    }
}

__global__ void __launch_bounds__(256, 5)
fused_kernel(const float* __restrict__ pred_cls,
             const float* __restrict__ pred_response,
             const float* __restrict__ pred_bboxes,
             const float* __restrict__ tgt_box,
             const int*   __restrict__ tix,
             const int*   __restrict__ tiy,
             const int*   __restrict__ tib,
             const int*   __restrict__ tlab,
             float* __restrict__ out)
{
    int lane = threadIdx.x & 31;
    int wrp  = threadIdx.x >> 5;
    __shared__ float sm[8][5];

    if (blockIdx.x >= TGT_BLOCKS) {
        // ---------------- negative-response pass: 2 vec4 units per thread ----------------
        int u0 = (blockIdx.x - TGT_BLOCKS) * 512 + threadIdx.x;  // coalesced pair
        int u1 = u0 + 256;
        bool ok0 = (u0 < NUNITS);
        bool ok1 = (u1 < NUNITS);

        // ---- load phase: issue all independent loads up front (MLP=10) ----
        float4 A0, A1, AW, AH, AR;   // unit0
        float4 B0, B1, BW, BH, BR;   // unit1
        int ba0 = 0, p0i = 0, ba1 = 0, p1i = 0;
        if (ok0) {
            ba0 = u0 / QWn;
            p0i = (u0 - ba0 * QWn) * 4;
            const float4* pb = (const float4*)(pred_bboxes + (size_t)ba0 * 4 * HWn + p0i);
            A0 = pb[0]; A1 = pb[QWn]; AW = pb[2 * QWn]; AH = pb[3 * QWn];
            AR = ((const float4*)(pred_response + (size_t)ba0 * HWn + p0i))[0];
        }
        if (ok1) {
            ba1 = u1 / QWn;
            p1i = (u1 - ba1 * QWn) * 4;
            const float4* pb = (const float4*)(pred_bboxes + (size_t)ba1 * 4 * HWn + p1i);
            B0 = pb[0]; B1 = pb[QWn]; BW = pb[2 * QWn]; BH = pb[3 * QWn];
            BR = ((const float4*)(pred_response + (size_t)ba1 * HWn + p1i))[0];
        }

        float acc = 0.f;
        #pragma unroll
        for (int uu = 0; uu < 2; uu++) {
            bool ok = uu ? ok1 : ok0;
            if (!ok) continue;
            int ba = uu ? ba1 : ba0;
            int p  = uu ? p1i : p0i;
            int b  = ba / An;
            int h  = p / Wn;
            int w  = p - h * Wn;

            float P0[4], P1[4], PW[4], PH[4], PR[4];
            {
                float4 v0 = uu ? B0 : A0, v1 = uu ? B1 : A1;
                float4 vw = uu ? BW : AW, vh = uu ? BH : AH, vr = uu ? BR : AR;
                P0[0]=v0.x; P0[1]=v0.y; P0[2]=v0.z; P0[3]=v0.w;
                P1[0]=v1.x; P1[1]=v1.y; P1[2]=v1.z; P1[3]=v1.w;
                PW[0]=vw.x; PW[1]=vw.y; PW[2]=vw.z; PW[3]=vw.w;
                PH[0]=vh.x; PH[1]=vh.y; PH[2]=vh.z; PH[3]=vh.w;
                PR[0]=vr.x; PR[1]=vr.y; PR[2]=vr.z; PR[3]=vr.w;
            }

            // last target of batch b (L1/L2 resident, broadcast)
            const float* tb = tgt_box + ((size_t)b * Tn + (Tn - 1)) * 4;
            float tw  = tb[2], th = tb[3];
            float gx1 = tb[0] + (float)tix[b * Tn + Tn - 1] - tw * 0.5f;
            float gy1 = tb[1] + (float)tiy[b * Tn + Tn - 1] - th * 0.5f;
            float gx2 = gx1 + tw, gy2 = gy1 + th;
            float tarea = tw * th;

            float fh = (float)h;
            #pragma unroll
            for (int j = 0; j < 4; j++) {
                float pw_ = PW[j], ph_ = PH[j];
                float hpw = pw_ * 0.5f, hph = ph_ * 0.5f;
                float pwph = pw_ * ph_;
                float fw = (float)(w + j);

                // Interval bound over sigmoid in (0,1): exact implication iou < 0.6
                float dxu = fminf(fw + 1.f + hpw, gx2) - fmaxf(fw - hpw, gx1);
                float dyu = fminf(fh + 1.f + hph, gy2) - fmaxf(fh - hph, gy1);
                float iu  = fmaxf(dxu, 0.f) * fmaxf(dyu, 0.f);

                bool neg;
                if (iu < 0.6f * (pwph + tarea - iu)) {
                    neg = true;                            // provably iou < 0.6
                } else {
                    float px1 = fsigmoid(P0[j]) + fw - hpw;
                    float py1 = fsigmoid(P1[j]) + fh - hph;
                    float dx    = fmaxf(fminf(px1 + pw_, gx2) - fmaxf(px1, gx1), 0.f);
                    float dy    = fmaxf(fminf(py1 + ph_, gy2) - fmaxf(py1, gy1), 0.f);
                    float inter = dx * dy;
                    float iou   = inter / (pwph + tarea - inter);
                    neg = (iou < 0.6f);
                }
                if (neg) acc += softplusf_(PR[j]);
            }
        }

        #pragma unroll
        for (int o = 16; o; o >>= 1) acc += __shfl_xor_sync(0xffffffffu, acc, o);
        if (lane == 0) sm[wrp][0] = acc;
        __syncthreads();
        if (threadIdx.x == 0) {
            float v = 0.f;
            #pragma unroll
            for (int i = 0; i < 8; i++) v += sm[i][0];
            atomicAdd(&g_scratch[1], v * (0.5f / Bn));   // L_NOOBJ / B
        }
        ticket_and_finalize(out);
    } else {
        // ---------------- per-target pass (1 warp per target), blocks 0..255 ----------------
        int gw = blockIdx.x * 8 + wrp;  // 0..2047
        int bt = gw;
        int b  = gw / Tn;

        int x   = tix[bt];
        int y   = tiy[bt];
        int a   = tib[bt];
        int lab = tlab[bt];

        const float* tb = tgt_box + (size_t)bt * 4;
        float tx = tb[0], ty = tb[1], tw = tb[2], th = tb[3];

        int sp = y * Wn + x;
        int ba = b * An + a;
        const float* pbp = pred_bboxes + (size_t)ba * 4 * HWn + sp;
        float p0 = pbp[0], p1 = pbp[HWn], pw_ = pbp[2 * HWn], ph_ = pbp[3 * HWn];

        // ---- class CE (warp-collective over C=80) ----
        const float* pc = pred_cls + (size_t)ba * Cn * HWn + sp;
        float lv0 = pc[(size_t)lane * HWn];
        float lv1 = pc[(size_t)(lane + 32) * HWn];
        float lv2 = (lane + 64 < Cn) ? pc[(size_t)(lane + 64) * HWn] : -INFINITY;

        float m = fmaxf(lv0, fmaxf(lv1, lv2));
        #pragma unroll
        for (int o = 16; o; o >>= 1) m = fmaxf(m, __shfl_xor_sync(0xffffffffu, m, o));

        float s = __expf(lv0 - m) + __expf(lv1 - m);
        float ll = 0.f;
        if (lane == lab)      ll = lv0;
        if (lane + 32 == lab) ll = lv1;
        if (lane + 64 < Cn) {
            s += __expf(lv2 - m);
            if (lane + 64 == lab) ll = lv2;
        }
        #pragma unroll
        for (int o = 16; o; o >>= 1) {
            s  += __shfl_xor_sync(0xffffffffu, s, o);
            ll += __shfl_xor_sync(0xffffffffu, ll, o);
        }
        float loss_cls = m + __logf(s) - ll;

        float loss_pos = 0.f, neg_sub = 0.f, loss_xy = 0.f, loss_wh = 0.f;
        if (lane == 0) {
            float px1 = fsigmoid(p0) + (float)x - pw_ * 0.5f;
            float py1 = fsigmoid(p1) + (float)y - ph_ * 0.5f;

            float gx1 = tx + (float)x - tw * 0.5f;
            float gy1 = ty + (float)y - th * 0.5f;
            float dx    = fmaxf(fminf(px1 + pw_, gx1 + tw) - fmaxf(px1, gx1), 0.f);
            float dy    = fmaxf(fminf(py1 + ph_, gy1 + th) - fmaxf(py1, gy1), 0.f);
            float inter = dx * dy;
            float iou_sel = inter / (pw_ * ph_ + tw * th - inter);

            float prr = pred_response[(size_t)ba * HWn + sp];
            loss_pos = softplusf_(prr) - prr * iou_sel;

            // neg-mask correction at this (unique) pos position
            const float* tb2 = tgt_box + ((size_t)b * Tn + Tn - 1) * 4;
            float tw2  = tb2[2], th2 = tb2[3];
            float g2x1 = tb2[0] + (float)tix[b * Tn + Tn - 1] - tw2 * 0.5f;
            float g2y1 = tb2[1] + (float)tiy[b * Tn + Tn - 1] - th2 * 0.5f;
            float dx2    = fmaxf(fminf(px1 + pw_, g2x1 + tw2) - fmaxf(px1, g2x1), 0.f);
            float dy2    = fmaxf(fminf(py1 + ph_, g2y1 + th2) - fmaxf(py1, g2y1), 0.f);
            float inter2 = dx2 * dy2;
            float iou2   = inter2 / (pw_ * ph_ + tw2 * th2 - inter2);
            if (iou2 < 0.6f) neg_sub = softplusf_(prr);

            loss_xy = (softplusf_(p0) - p0 * tx) + (softplusf_(p1) - p1 * ty);
            loss_wh = (pw_ - tw) * (pw_ - tw) + (ph_ - th) * (ph_ - th);
        }

        if (lane == 0) {
            sm[wrp][0] = loss_pos;
            sm[wrp][1] = -neg_sub;
            sm[wrp][2] = loss_cls;
            sm[wrp][3] = loss_xy;
            sm[wrp][4] = loss_wh;
        }
        __syncthreads();
        if (threadIdx.x < 5) {
            float v = 0.f;
            #pragma unroll
            for (int i = 0; i < 8; i++) v += sm[i][threadIdx.x];
            const float scales[5] = {1.0f / Bn, 0.5f / Bn, 1.0f / Bn, 1.0f / Bn, 5.0f / Bn};
            atomicAdd(&g_scratch[threadIdx.x], v * scales[threadIdx.x]);
        }
        ticket_and_finalize(out);
    }
}

extern "C" void kernel_launch(void* const* d_in, const int* in_sizes, int n_in,
                              void* d_out, int out_size)
{
    const float* pred_cls      = (const float*)d_in[0];
    const float* pred_response = (const float*)d_in[1];
    const float* pred_bboxes   = (const float*)d_in[2];
    const float* tgt_box       = (const float*)d_in[3];
    const int*   tgt_idx_x     = (const int*)d_in[4];
    const int*   tgt_idx_y     = (const int*)d_in[5];
    const int*   tgt_idx_box   = (const int*)d_in[6];
    const int*   tgt_label     = (const int*)d_in[7];
    float* out = (float*)d_out;

    fused_kernel<<<GRID, 256>>>(pred_cls, pred_response, pred_bboxes,
                                tgt_box, tgt_idx_x, tgt_idx_y,
                                tgt_idx_box, tgt_label, out);
}

// round 10
// speedup vs baseline: 1.5038x; 1.5038x over previous
#include <cuda_runtime.h>

// Problem constants
#define Bn  64
#define An  5
#define Cn  80
#define Hn  52
#define Wn  52
#define Tn  32
#define HWn (Hn * Wn)          // 2704
#define QWn (HWn / 4)          // 676 float4s per plane

#define TGT_BLOCKS 256          // 2048 warps / 8
#define NEG_BLOCKS 845          // 216320 vec4-units / 256
#define GRID (TGT_BLOCKS + NEG_BLOCKS)   // 1101 <= 1184 (8 blocks/SM * 148)

// Persistent scratch (zero at module load; final block resets after each run)
__device__ float        g_scratch[5];
__device__ unsigned int g_count;

__device__ __forceinline__ float softplusf_(float x) {
    // max(x,0) + log(1 + exp(-|x|));  EX2 + LG2, abs err ~1e-7
    return fmaxf(x, 0.f) + __logf(1.f + __expf(-fabsf(x)));
}
__device__ __forceinline__ float fsigmoid(float x) {
    // sigmoid(x) = 0.5 + 0.5*tanh(x/2) — HW MUFU.TANH, abs err ~1e-5
    float t;
    asm("tanh.approx.f32 %0, %1;" : "=f"(t) : "f"(x * 0.5f));
    return fmaf(t, 0.5f, 0.5f);
}

__device__ __forceinline__ void ticket_and_finalize(float* __restrict__ out) {
    __shared__ bool is_last;
    __threadfence();
    if (threadIdx.x == 0) {
        unsigned prev = atomicAdd(&g_count, 1u);
        is_last = (prev == GRID - 1);
    }
    __syncthreads();
    if (is_last) {
        __threadfence();
        if (threadIdx.x < 5) {
            volatile float* vs = g_scratch;
            out[threadIdx.x] = vs[threadIdx.x];
            g_scratch[threadIdx.x] = 0.f;
        }
        if (threadIdx.x == 0) g_count = 0u;
    }
}

__global__ void __launch_bounds__(256, 8)
fused_kernel(const float* __restrict__ pred_cls,
             const float* __restrict__ pred_response,
             const float* __restrict__ pred_bboxes,
             const float* __restrict__ tgt_box,
             const int*   __restrict__ tix,
             const int*   __restrict__ tiy,
             const int*   __restrict__ tib,
             const int*   __restrict__ tlab,
             float* __restrict__ out)
{
    int lane = threadIdx.x & 31;
    int wrp  = threadIdx.x >> 5;
    __shared__ float sm[8][5];

    if (blockIdx.x >= TGT_BLOCKS) {
        // ---------------- negative-response pass (1 vec4 unit / thread, MLP=5) ----------------
        int t  = (blockIdx.x - TGT_BLOCKS) * 256 + threadIdx.x;   // 0..216319 exact
        int ba = t / QWn;                              // b*A + a
        int p  = (t - ba * QWn) * 4;                   // pixel base (row-aligned)
        int b  = ba / An;
        int h  = p / Wn;
        int w  = p - h * Wn;

        const float4* pb = (const float4*)(pred_bboxes + (size_t)ba * 4 * HWn + p);
        float4 v0 = pb[0];
        float4 v1 = pb[QWn];
        float4 vw = pb[2 * QWn];
        float4 vh = pb[3 * QWn];
        float4 pr = ((const float4*)(pred_response + (size_t)ba * HWn + p))[0];

        // last target of batch b (L2/L1 resident, broadcast)
        const float* tb = tgt_box + ((size_t)b * Tn + (Tn - 1)) * 4;
        float tw  = tb[2], th = tb[3];
        float gx1 = tb[0] + (float)tix[b * Tn + Tn - 1] - tw * 0.5f;
        float gy1 = tb[1] + (float)tiy[b * Tn + Tn - 1] - th * 0.5f;
        float gx2 = gx1 + tw, gy2 = gy1 + th;
        float tarea = tw * th;

        float P0[4] = {v0.x, v0.y, v0.z, v0.w};
        float P1[4] = {v1.x, v1.y, v1.z, v1.w};
        float PW[4] = {vw.x, vw.y, vw.z, vw.w};
        float PH[4] = {vh.x, vh.y, vh.z, vh.w};
        float PR[4] = {pr.x, pr.y, pr.z, pr.w};

        float fh = (float)h;
        float acc = 0.f;
        #pragma unroll
        for (int j = 0; j < 4; j++) {
            float pw_ = PW[j], ph_ = PH[j];
            float hpw = pw_ * 0.5f, hph = ph_ * 0.5f;
            float pwph = pw_ * ph_;
            float fw = (float)(w + j);

            // Interval bound over sigmoid in (0,1): exact implication iou < 0.6
            float dxu = fminf(fw + 1.f + hpw, gx2) - fmaxf(fw - hpw, gx1);
            float dyu = fminf(fh + 1.f + hph, gy2) - fmaxf(fh - hph, gy1);
            float iu  = fmaxf(dxu, 0.f) * fmaxf(dyu, 0.f);

            bool neg;
            if (iu < 0.6f * (pwph + tarea - iu)) {
                neg = true;                            // provably iou < 0.6
            } else {
                float px1 = fsigmoid(P0[j]) + fw - hpw;
                float py1 = fsigmoid(P1[j]) + fh - hph;
                float dx    = fmaxf(fminf(px1 + pw_, gx2) - fmaxf(px1, gx1), 0.f);
                float dy    = fmaxf(fminf(py1 + ph_, gy2) - fmaxf(py1, gy1), 0.f);
                float inter = dx * dy;
                float iou   = inter / (pwph + tarea - inter);
                neg = (iou < 0.6f);
            }
            if (neg) acc += softplusf_(PR[j]);
        }

        #pragma unroll
        for (int o = 16; o; o >>= 1) acc += __shfl_xor_sync(0xffffffffu, acc, o);
        if (lane == 0) sm[wrp][0] = acc;
        __syncthreads();
        if (threadIdx.x == 0) {
            float v = 0.f;
            #pragma unroll
            for (int i = 0; i < 8; i++) v += sm[i][0];
            atomicAdd(&g_scratch[1], v * (0.5f / Bn));   // L_NOOBJ / B
        }
        ticket_and_finalize(out);
    } else {
        // ---------------- per-target pass (1 warp per target), blocks 0..255 ----------------
        int gw = blockIdx.x * 8 + wrp;  // 0..2047
        int bt = gw;
        int b  = gw / Tn;

        int x   = tix[bt];
        int y   = tiy[bt];
        int a   = tib[bt];
        int lab = tlab[bt];

        const float* tb = tgt_box + (size_t)bt * 4;
        float tx = tb[0], ty = tb[1], tw = tb[2], th = tb[3];

        int sp = y * Wn + x;
        int ba = b * An + a;
        const float* pbp = pred_bboxes + (size_t)ba * 4 * HWn + sp;
        float p0 = pbp[0], p1 = pbp[HWn], pw_ = pbp[2 * HWn], ph_ = pbp[3 * HWn];

        // ---- class CE (warp-collective over C=80) ----
        const float* pc = pred_cls + (size_t)ba * Cn * HWn + sp;
        float lv0 = pc[(size_t)lane * HWn];
        float lv1 = pc[(size_t)(lane + 32) * HWn];
        float lv2 = (lane + 64 < Cn) ? pc[(size_t)(lane + 64) * HWn] : -INFINITY;

        float m = fmaxf(lv0, fmaxf(lv1, lv2));
        #pragma unroll
        for (int o = 16; o; o >>= 1) m = fmaxf(m, __shfl_xor_sync(0xffffffffu, m, o));

        float s = __expf(lv0 - m) + __expf(lv1 - m);
        float ll = 0.f;
        if (lane == lab)      ll = lv0;
        if (lane + 32 == lab) ll = lv1;
        if (lane + 64 < Cn) {
            s += __expf(lv2 - m);
            if (lane + 64 == lab) ll = lv2;
        }
        #pragma unroll
        for (int o = 16; o; o >>= 1) {
            s  += __shfl_xor_sync(0xffffffffu, s, o);
            ll += __shfl_xor_sync(0xffffffffu, ll, o);
        }
        float loss_cls = m + __logf(s) - ll;

        float loss_pos = 0.f, neg_sub = 0.f, loss_xy = 0.f, loss_wh = 0.f;
        if (lane == 0) {
            float px1 = fsigmoid(p0) + (float)x - pw_ * 0.5f;
            float py1 = fsigmoid(p1) + (float)y - ph_ * 0.5f;

            float gx1 = tx + (float)x - tw * 0.5f;
            float gy1 = ty + (float)y - th * 0.5f;
            float dx    = fmaxf(fminf(px1 + pw_, gx1 + tw) - fmaxf(px1, gx1), 0.f);
            float dy    = fmaxf(fminf(py1 + ph_, gy1 + th) - fmaxf(py1, gy1), 0.f);
            float inter = dx * dy;
            float iou_sel = inter / (pw_ * ph_ + tw * th - inter);

            float prr = pred_response[(size_t)ba * HWn + sp];
            loss_pos = softplusf_(prr) - prr * iou_sel;

            // neg-mask correction at this (unique) pos position
            const float* tb2 = tgt_box + ((size_t)b * Tn + Tn - 1) * 4;
            float tw2  = tb2[2], th2 = tb2[3];
            float g2x1 = tb2[0] + (float)tix[b * Tn + Tn - 1] - tw2 * 0.5f;
            float g2y1 = tb2[1] + (float)tiy[b * Tn + Tn - 1] - th2 * 0.5f;
            float dx2    = fmaxf(fminf(px1 + pw_, g2x1 + tw2) - fmaxf(px1, g2x1), 0.f);
            float dy2    = fmaxf(fminf(py1 + ph_, g2y1 + th2) - fmaxf(py1, g2y1), 0.f);
            float inter2 = dx2 * dy2;
            float iou2   = inter2 / (pw_ * ph_ + tw2 * th2 - inter2);
            if (iou2 < 0.6f) neg_sub = softplusf_(prr);

            loss_xy = (softplusf_(p0) - p0 * tx) + (softplusf_(p1) - p1 * ty);
            loss_wh = (pw_ - tw) * (pw_ - tw) + (ph_ - th) * (ph_ - th);
        }

        if (lane == 0) {
            sm[wrp][0] = loss_pos;
            sm[wrp][1] = -neg_sub;
            sm[wrp][2] = loss_cls;
            sm[wrp][3] = loss_xy;
            sm[wrp][4] = loss_wh;
        }
        __syncthreads();
        if (threadIdx.x < 5) {
            float v = 0.f;
            #pragma unroll
            for (int i = 0; i < 8; i++) v += sm[i][threadIdx.x];
            const float scales[5] = {1.0f / Bn, 0.5f / Bn, 1.0f / Bn, 1.0f / Bn, 5.0f / Bn};
            atomicAdd(&g_scratch[threadIdx.x], v * scales[threadIdx.x]);
        }
        ticket_and_finalize(out);
    }
}

extern "C" void kernel_launch(void* const* d_in, const int* in_sizes, int n_in,
                              void* d_out, int out_size)
{
    const float* pred_cls      = (const float*)d_in[0];
    const float* pred_response = (const float*)d_in[1];
    const float* pred_bboxes   = (const float*)d_in[2];
    const float* tgt_box       = (const float*)d_in[3];
    const int*   tgt_idx_x     = (const int*)d_in[4];
    const int*   tgt_idx_y     = (const int*)d_in[5];
    const int*   tgt_idx_box   = (const int*)d_in[6];
    const int*   tgt_label     = (const int*)d_in[7];
    float* out = (float*)d_out;

    fused_kernel<<<GRID, 256>>>(pred_cls, pred_response, pred_bboxes,
                                tgt_box, tgt_idx_x, tgt_idx_y,
                                tgt_idx_box, tgt_label, out);
}